// round 10
// baseline (speedup 1.0000x reference)
#include <cuda_runtime.h>
#include <cstdint>
#include <cstring>

#define BB 4
#define NN 4096
#define DD 1024
#define EE 64
#define CAP 128
#define NT (BB*NN)                       // 16384 tokens
#define BNEC ((size_t)NT*EE*CAP)         // 134217728 elements per big tensor
#define THRESH 0.2f
#define NB 256                           // gating blocks (64 tokens each)

// zero-fill partition (in float4 units): total = 2*BNEC/4 = 67,108,864
#define TOT4   67108864UL
#define K2Z4   6291456UL                 // 96 MiB handled during scan window
#define K1Z4   (TOT4 - K2Z4)             // 60,817,408 float4
#define NZB    1856                      // K1 zero blocks: 1856 * 32768 float4 = K1Z4
#define K2ZB   384                       // zero blocks in K2
#define K2LANES (K2ZB*1024)              // 393216 lanes * 16 = K2Z4
#define K2PER  16

// packed dual-FMA: acc(2xf32) += a(2xf32) * b(2xf32), elementwise
#define FFMA2(acc, a, b) \
    asm("fma.rn.f32x2 %0, %1, %2, %0;" : "+l"(acc) : "l"(a), "l"(b))

// ---------------- scratch (no allocations allowed) ----------------
__device__ int   g_idx1[NT], g_idx2[NT];
__device__ float g_g1[NT],  g_g2[NT];
__device__ int   g_pos1[NT], g_pos2[NT];
__device__ float g_dens_p[NB][EE];       // per-gating-block partials (no atomics, no init)
__device__ int   g_cnt_p[NB][EE];        // per-chunk top-1 histogram (doubles as scan input)
__device__ int   g_cnt2_p[NB][EE];       // per-chunk thresholded top-2 histogram
__device__ float g_lse_p[NB];

// ---------------- K1: heterogeneous blocks ----------------
// bid < NB   : GEMM (FFMA2 inner loop) + softmax + top2 + aux partials + chunk histograms
// bid >= NB  : pure zero-writer block, contiguous 128 KiB each
__global__ __launch_bounds__(256) void fused_kernel(const float* __restrict__ x,
                                                    const float* __restrict__ w,
                                                    float* __restrict__ out) {
    const int tid = threadIdx.x;
    const int bid = blockIdx.x;

    // ======== zero-writer blocks ========
    if (bid >= NB) {
        const size_t base = (size_t)(bid - NB) * 32768 + tid;
        float4* __restrict__ o4 = (float4*)out;
        const float4 z4 = make_float4(0.f, 0.f, 0.f, 0.f);
        #pragma unroll 1
        for (int g = 0; g < 4; g++) {
            const size_t q = base + (size_t)g * 8 * 256;
            #pragma unroll
            for (int i = 0; i < 8; i++)
                __stcs(&o4[q + (size_t)i * 256], z4);
        }
        return;
    }

    // ======== GEMM blocks: 64 tokens x 64 experts, FFMA2 ========
    __shared__ float xs[16][64];       // [k][token] (tokens contiguous -> natural f32x2 pairs)
    __shared__ float wsd[16][128];     // [k][expert duplicated]: wsd[k][2e]=wsd[k][2e+1]=w[k][e]
    __shared__ float logits[64][65];   // padded; later overwritten in-place by probs
    __shared__ float sm_invS[64];
    __shared__ int   scnt[64];
    __shared__ int   scnt2[64];

    const int t0 = bid * 64;
    const int eg = tid & 15, tg = tid >> 4;

    // acc pairs: accp[tp][j] = {tok tg*4+2tp, tok tg*4+2tp+1} x expert eg*4+j
    unsigned long long accp[2][4];
    #pragma unroll
    for (int i = 0; i < 2; i++)
        #pragma unroll
        for (int j = 0; j < 4; j++) accp[i][j] = 0ull;

    const int xtok = tid >> 2, xkq = tid & 3;   // x-tile loader mapping
    const int wkk  = tid >> 4, weq = tid & 15;  // w-tile loader mapping

    const float4* xg = (const float4*)(x) + (size_t)(t0 + xtok) * (DD/4) + xkq;
    const float4* wg = (const float4*)(w) + (size_t)wkk * (EE/4) + weq;

    float4 xv = __ldcs(xg);
    float4 wv = wg[0];

    for (int kc = 0; kc < DD/16; kc++) {
        __syncthreads();
        xs[xkq*4+0][xtok] = xv.x;
        xs[xkq*4+1][xtok] = xv.y;
        xs[xkq*4+2][xtok] = xv.z;
        xs[xkq*4+3][xtok] = xv.w;
        *(float4*)&wsd[wkk][weq*8]     = make_float4(wv.x, wv.x, wv.y, wv.y);
        *(float4*)&wsd[wkk][weq*8 + 4] = make_float4(wv.z, wv.z, wv.w, wv.w);
        __syncthreads();
        if (kc < DD/16 - 1) {
            xv = __ldcs(xg + (size_t)(kc+1)*4);   // +16 floats along D
            wv = wg[(size_t)(kc+1)*16*(EE/4)];    // +16 rows of w
        }
        #pragma unroll
        for (int kk = 0; kk < 16; kk++) {
            const ulonglong2 xp  = *(const ulonglong2*)&xs[kk][tg*4];       // 2 token-pairs
            const ulonglong2 b01 = *(const ulonglong2*)&wsd[kk][eg*8];      // {b0,b0},{b1,b1}
            const ulonglong2 b23 = *(const ulonglong2*)&wsd[kk][eg*8 + 4];  // {b2,b2},{b3,b3}
            FFMA2(accp[0][0], xp.x, b01.x);
            FFMA2(accp[0][1], xp.x, b01.y);
            FFMA2(accp[0][2], xp.x, b23.x);
            FFMA2(accp[0][3], xp.x, b23.y);
            FFMA2(accp[1][0], xp.y, b01.x);
            FFMA2(accp[1][1], xp.y, b01.y);
            FFMA2(accp[1][2], xp.y, b23.x);
            FFMA2(accp[1][3], xp.y, b23.y);
        }
    }

    #pragma unroll
    for (int tp = 0; tp < 2; tp++)
        #pragma unroll
        for (int j = 0; j < 4; j++) {
            float2 v;
            memcpy(&v, &accp[tp][j], 8);
            logits[tg*4 + 2*tp + 0][eg*4 + j] = v.x;
            logits[tg*4 + 2*tp + 1][eg*4 + j] = v.y;
        }

    if (tid < 64) { scnt[tid] = 0; scnt2[tid] = 0; }
    __syncthreads();

    float my_lse = 0.f;
    if (tid < 64) {
        const int t = tid;
        // top-2 over logits (softmax monotonic; strict > keeps first index on ties)
        float best1 = -3.4e38f, best2 = -3.4e38f;
        int i1 = 0, i2 = 0;
        #pragma unroll 4
        for (int e = 0; e < EE; e++) {
            float l = logits[t][e];
            if (l > best1) { best2 = best1; i2 = i1; best1 = l; i1 = e; }
            else if (l > best2) { best2 = l; i2 = e; }
        }
        float S = 0.f;
        #pragma unroll 4
        for (int e = 0; e < EE; e++) {
            float p = __expf(logits[t][e] - best1);
            logits[t][e] = p;                    // in-place: row t owned by thread t
            S += p;
        }
        float invS = 1.0f / S;
        sm_invS[t] = invS;
        float g1 = invS;                         // exp(best1-best1)*invS
        float g2 = __expf(best2 - best1) * invS;
        float denom = g1 + g2 + 1e-9f;
        float g1n = g1 / denom, g2n = g2 / denom;
        g_idx1[t0 + t] = i1;
        g_idx2[t0 + t] = i2;
        g_g1[t0 + t] = g1n;
        g_g2[t0 + t] = g2n;
        atomicAdd(&scnt[i1], 1);
        if (g2n > THRESH) atomicAdd(&scnt2[i2], 1);
        my_lse = best1 + __logf(S);
    }
    __syncthreads();

    if (tid < 64) {
        // density: column sums of the in-place prob matrix
        float s = 0.f;
        #pragma unroll 4
        for (int t = 0; t < 64; t++) s += logits[t][tid] * sm_invS[t];
        g_dens_p[bid][tid] = s;
        g_cnt_p[bid][tid]  = scnt[tid];
        g_cnt2_p[bid][tid] = scnt2[tid];
        // warp-reduce lse across the 2 warps holding tid<64
        #pragma unroll
        for (int o = 16; o > 0; o >>= 1)
            my_lse += __shfl_down_sync(0xffffffffu, my_lse, o);
        if ((tid & 31) == 0) {
            if (tid == 0) sm_invS[0] = my_lse;   // reuse smem slot
            else          sm_invS[1] = my_lse;
        }
    }
    __syncthreads();
    if (tid == 0) g_lse_p[bid] = sm_invS[0] + sm_invS[1];
}

// ---------------- K2: chunk-parallel scan (blocks 0..3) + zero-fill (blocks 4..387) ----------------
__global__ __launch_bounds__(1024) void scan_zero_kernel(float* __restrict__ out) {
    // ---- zero-fill blocks: cover the last 96 MiB while the scan runs ----
    if (blockIdx.x >= 4) {
        const unsigned lane = (blockIdx.x - 4) * 1024u + threadIdx.x;
        float4* __restrict__ o4 = (float4*)out + K1Z4;
        const float4 z4 = make_float4(0.f, 0.f, 0.f, 0.f);
        size_t q = lane;
        #pragma unroll
        for (int i = 0; i < K2PER; i++) {
            __stcs(&o4[q], z4);
            q += (size_t)K2LANES;
        }
        return;
    }

    __shared__ int s_c1[64][64];     // chunk-hist, overwritten in-place by exclusive prefix
    __shared__ int s_c2[64][64];
    __shared__ int hist1[16][64];    // per-pass lower-half-warp histograms
    __shared__ int hist2[16][64];

    const int b    = blockIdx.x;
    const int tid  = threadIdx.x;
    const int wid  = tid >> 5;
    const int lane = tid & 31;
    const unsigned lt = (1u << lane) - 1u;

    // load 64 chunks x 64 experts (int4-coalesced)
    ((int4*)s_c1)[tid] = ((const int4*)g_cnt_p)[b*1024 + tid];
    ((int4*)s_c2)[tid] = ((const int4*)g_cnt2_p)[b*1024 + tid];
    __syncthreads();

    // per-expert exclusive prefix over chunks; phase-2 base = capped phase-1 total
    if (tid < 64) {
        int run = 0;
        #pragma unroll 8
        for (int c = 0; c < 64; c++) { int v = s_c1[c][tid]; s_c1[c][tid] = run; run += v; }
        int run2 = min(run, CAP);
        #pragma unroll 8
        for (int c = 0; c < 64; c++) { int v = s_c2[c][tid]; s_c2[c][tid] = run2; run2 += v; }
    }
    __syncthreads();

    // 4 passes x 1024 tokens; each 64-token chunk spans exactly 2 warps
    for (int pass = 0; pass < 4; pass++) {
        const int li = pass * 1024 + tid;    // token index within batch
        const int t  = b * NN + li;
        const int ch = li >> 6;              // chunk within batch (0..63)
        const int hc = tid >> 6;             // chunk within this pass (0..15)
        const bool upper = (wid & 1);

        ((int*)hist1)[tid] = 0;
        ((int*)hist2)[tid] = 0;
        __syncthreads();

        const int e1   = g_idx1[t];
        const bool v2  = g_g2[t] > THRESH;
        const int e2   = v2 ? g_idx2[t] : -1;

        unsigned m1 = __match_any_sync(0xffffffffu, e1);
        int r1 = __popc(m1 & lt);
        unsigned m2 = __match_any_sync(0xffffffffu, e2);
        int r2 = __popc(m2 & lt);

        if (!upper) {
            if (r1 == 0) hist1[hc][e1] = __popc(m1);
            if (v2 && r2 == 0) hist2[hc][e2] = __popc(m2);
        }
        __syncthreads();

        if (upper) {
            r1 += hist1[hc][e1];
            if (v2) r2 += hist2[hc][e2];
        }

        int p1 = s_c1[ch][e1] + r1;
        g_pos1[t] = (p1 < CAP) ? p1 : -1;
        if (v2) {
            int p2 = s_c2[ch][e2] + r2;
            g_pos2[t] = (p2 < CAP) ? p2 : -1;
        } else {
            g_pos2[t] = -1;
        }
        __syncthreads();
    }
}

// ---------------- K3: scatter nonzeros + finalize scalars (block 0) ----------------
__global__ __launch_bounds__(256) void scatter_finalize_kernel(float* __restrict__ out) {
    const int t = blockIdx.x * 256 + threadIdx.x;

    if (t < NT) {
        const int p1 = g_pos1[t], p2 = g_pos2[t];
        const size_t row = (size_t)t * (EE*CAP);

        if (p1 >= 0) {
            const size_t o = row + (size_t)g_idx1[t] * CAP + p1;
            out[o]        = 1.f;       // dispatch
            out[BNEC + o] = g_g1[t];   // combine
        }
        if (p2 >= 0) {
            const size_t o = row + (size_t)g_idx2[t] * CAP + p2;
            out[o]        = 1.f;
            out[BNEC + o] = g_g2[t];
        }
    }

    if (blockIdx.x == 0) {
        __shared__ float red[256];
        const int tid = threadIdx.x;
        const int b = tid >> 6, e = tid & 63;

        // reconstruct per-(batch,expert) dens & count from the 64 chunk partials
        float dens = 0.f; int cnt = 0;
        #pragma unroll 8
        for (int c = 0; c < 64; c++) {
            dens += g_dens_p[b*64 + c][e];
            cnt  += g_cnt_p[b*64 + c][e];
        }
        red[tid] = dens * (float)cnt;
        __syncthreads();
        for (int s = 128; s > 0; s >>= 1) {
            if (tid < s) red[tid] += red[tid + s];
            __syncthreads();
        }
        float loss = red[0] * ((float)EE / ((float)BB * (float)NN * (float)NN));
        __syncthreads();

        red[tid] = g_lse_p[tid];
        __syncthreads();
        for (int s = 128; s > 0; s >>= 1) {
            if (tid < s) red[tid] += red[tid + s];
            __syncthreads();
        }
        if (tid == 0) {
            out[2*BNEC]     = loss;
            out[2*BNEC + 1] = red[0] * (1.0f / (float)BB);
        }
    }
}

// ---------------- launch ----------------
extern "C" void kernel_launch(void* const* d_in, const int* in_sizes, int n_in,
                              void* d_out, int out_size) {
    const float* x = (const float*)d_in[0];   // [4,4096,1024] f32
    const float* w = (const float*)d_in[1];   // [1024,64] f32
    float* out = (float*)d_out;               // dispatch | combine | loss | z_loss

    fused_kernel<<<NB + NZB, 256>>>(x, w, out);
    scan_zero_kernel<<<4 + K2ZB, 1024>>>(out);
    scatter_finalize_kernel<<<NT/256, 256>>>(out);
}

// round 12
// speedup vs baseline: 1.3900x; 1.3900x over previous
#include <cuda_runtime.h>
#include <cstdint>

#define BB 4
#define NN 4096
#define DD 1024
#define EE 64
#define CAP 128
#define NT (BB*NN)                       // 16384 tokens
#define BNEC ((size_t)NT*EE*CAP)         // 134217728 elements per big tensor
#define THRESH 0.2f
#define NB 256                           // gating blocks (64 tokens each)

// zero-fill partition (in float4 units): total = 2*BNEC/4 = 67,108,864
#define TOT4   67108864UL
#define K2Z4   6291456UL                 // 96 MiB handled during scan window (combine tail)
#define K1Z4   (TOT4 - K2Z4)             // 60,817,408 float4 (= element 243,269,632)
#define NZB    29696                     // K1 zero blocks: 29696 * 2048 = K1Z4
#define K2ZB   384                       // zero blocks in K2
#define K2LANES (K2ZB*1024)              // 393216 lanes * 16 = K2Z4
#define K2PER  16

// tokens >= T_DEFER have combine rows that may overlap K2's zero region:
// combine elem idx of token t ends at BNEC + (t+1)*8192; racing iff > K1Z4*4.
// boundary t = 13311; round down to 13056 (= 16384 - 13*256) for K3 grid alignment.
#define T_DEFER 13056
#define NDEF    (NT - T_DEFER)           // 3328 tokens -> 13 blocks of 256

// ---------------- scratch (no allocations allowed) ----------------
__device__ int   g_idx1[NT], g_idx2[NT];
__device__ float g_g1[NT],  g_g2[NT];
__device__ int   g_pos1[NT], g_pos2[NT];     // used only for t >= T_DEFER
__device__ float g_dens_p[NB][EE];           // per-gating-block partials (no atomics, no init)
__device__ int   g_cnt_p[NB][EE];            // per-chunk top-1 histogram (scan input)
__device__ int   g_cnt2_p[NB][EE];           // per-chunk thresholded top-2 histogram
__device__ float g_lse_p[NB];

// ---------------- K1: heterogeneous blocks (R9-proven, byte-identical) ----------------
// bid < NB   : GEMM + softmax + top2 + aux partials + per-chunk histograms
// bid >= NB  : pure zero-writer block, contiguous 32 KiB (proven 85.7%-DRAM pattern)
__global__ __launch_bounds__(256) void fused_kernel(const float* __restrict__ x,
                                                    const float* __restrict__ w,
                                                    float* __restrict__ out) {
    const int tid = threadIdx.x;
    const int bid = blockIdx.x;

    // ======== zero-writer blocks ========
    if (bid >= NB) {
        const size_t base = (size_t)(bid - NB) * 2048 + tid;
        float4* __restrict__ o4 = (float4*)out;
        const float4 z4 = make_float4(0.f, 0.f, 0.f, 0.f);
        #pragma unroll
        for (int i = 0; i < 8; i++)
            __stcs(&o4[base + (size_t)i * 256], z4);
        return;
    }

    // ======== GEMM blocks: 64 tokens x 64 experts ========
    __shared__ float xs[16][64];      // [k][token]
    __shared__ float ws[16][64];      // [k][expert]
    __shared__ float logits[64][65];  // padded; later overwritten in-place by probs
    __shared__ float sm_invS[64];
    __shared__ int   scnt[64];
    __shared__ int   scnt2[64];

    const int t0 = bid * 64;
    const int eg = tid & 15, tg = tid >> 4;

    float acc[4][4];
    #pragma unroll
    for (int i = 0; i < 4; i++)
        #pragma unroll
        for (int j = 0; j < 4; j++) acc[i][j] = 0.f;

    const int xtok = tid >> 2, xkq = tid & 3;   // x-tile loader mapping
    const int wkk  = tid >> 4, weq = tid & 15;  // w-tile loader mapping

    const float4* xg = (const float4*)(x) + (size_t)(t0 + xtok) * (DD/4) + xkq;
    const float4* wg = (const float4*)(w) + (size_t)wkk * (EE/4) + weq;

    float4 xv = xg[0];
    float4 wv = wg[0];

    for (int kc = 0; kc < DD/16; kc++) {
        __syncthreads();
        xs[xkq*4+0][xtok] = xv.x;
        xs[xkq*4+1][xtok] = xv.y;
        xs[xkq*4+2][xtok] = xv.z;
        xs[xkq*4+3][xtok] = xv.w;
        *(float4*)&ws[wkk][weq*4] = wv;
        __syncthreads();
        if (kc < DD/16 - 1) {
            xv = xg[(size_t)(kc+1)*4];            // +16 floats along D
            wv = wg[(size_t)(kc+1)*16*(EE/4)];    // +16 rows of w
        }
        #pragma unroll
        for (int kk = 0; kk < 16; kk++) {
            float4 a  = *(const float4*)&xs[kk][tg*4];
            float4 bv = *(const float4*)&ws[kk][eg*4];
            acc[0][0] += a.x*bv.x; acc[0][1] += a.x*bv.y; acc[0][2] += a.x*bv.z; acc[0][3] += a.x*bv.w;
            acc[1][0] += a.y*bv.x; acc[1][1] += a.y*bv.y; acc[1][2] += a.y*bv.z; acc[1][3] += a.y*bv.w;
            acc[2][0] += a.z*bv.x; acc[2][1] += a.z*bv.y; acc[2][2] += a.z*bv.z; acc[2][3] += a.z*bv.w;
            acc[3][0] += a.w*bv.x; acc[3][1] += a.w*bv.y; acc[3][2] += a.w*bv.z; acc[3][3] += a.w*bv.w;
        }
    }

    #pragma unroll
    for (int i = 0; i < 4; i++)
        #pragma unroll
        for (int j = 0; j < 4; j++)
            logits[tg*4+i][eg*4+j] = acc[i][j];

    if (tid < 64) { scnt[tid] = 0; scnt2[tid] = 0; }
    __syncthreads();

    float my_lse = 0.f;
    if (tid < 64) {
        const int t = tid;
        // top-2 over logits (softmax monotonic; strict > keeps first index on ties)
        float best1 = -3.4e38f, best2 = -3.4e38f;
        int i1 = 0, i2 = 0;
        #pragma unroll 4
        for (int e = 0; e < EE; e++) {
            float l = logits[t][e];
            if (l > best1) { best2 = best1; i2 = i1; best1 = l; i1 = e; }
            else if (l > best2) { best2 = l; i2 = e; }
        }
        float S = 0.f;
        #pragma unroll 4
        for (int e = 0; e < EE; e++) {
            float p = __expf(logits[t][e] - best1);
            logits[t][e] = p;                    // in-place: row t owned by thread t
            S += p;
        }
        float invS = 1.0f / S;
        sm_invS[t] = invS;
        float g1 = invS;                         // exp(best1-best1)*invS
        float g2 = __expf(best2 - best1) * invS;
        float denom = g1 + g2 + 1e-9f;
        float g1n = g1 / denom, g2n = g2 / denom;
        g_idx1[t0 + t] = i1;
        g_idx2[t0 + t] = i2;
        g_g1[t0 + t] = g1n;
        g_g2[t0 + t] = g2n;
        atomicAdd(&scnt[i1], 1);
        if (g2n > THRESH) atomicAdd(&scnt2[i2], 1);
        my_lse = best1 + __logf(S);
    }
    __syncthreads();

    if (tid < 64) {
        // density: column sums of the in-place prob matrix
        float s = 0.f;
        #pragma unroll 4
        for (int t = 0; t < 64; t++) s += logits[t][tid] * sm_invS[t];
        g_dens_p[bid][tid] = s;
        g_cnt_p[bid][tid]  = scnt[tid];
        g_cnt2_p[bid][tid] = scnt2[tid];
        // warp-reduce lse across the 2 warps holding tid<64
        #pragma unroll
        for (int o = 16; o > 0; o >>= 1)
            my_lse += __shfl_down_sync(0xffffffffu, my_lse, o);
        if ((tid & 31) == 0) {
            if (tid == 0) sm_invS[0] = my_lse;   // reuse smem slot
            else          sm_invS[1] = my_lse;
        }
    }
    __syncthreads();
    if (tid == 0) g_lse_p[bid] = sm_invS[0] + sm_invS[1];
}

// ---------------- K2: scan+safe-scatter (0..3) + finalize (4) + zero-fill (5..388) ----------------
// Scan blocks scatter inline everything that lands in K1's zero region (all dispatch
// writes; combine writes for t < T_DEFER). Combine writes for t >= T_DEFER would race
// with K2's own zero blocks -> positions recorded and drained by K3.
__global__ __launch_bounds__(1024) void scan_zero_kernel(float* __restrict__ out) {
    const int tid = threadIdx.x;

    // ---- zero-fill blocks: last 96 MiB (combine tail) ----
    if (blockIdx.x >= 5) {
        const unsigned lane = (blockIdx.x - 5) * 1024u + tid;
        float4* __restrict__ o4 = (float4*)out + K1Z4;
        const float4 z4 = make_float4(0.f, 0.f, 0.f, 0.f);
        size_t q = lane;
        #pragma unroll
        for (int i = 0; i < K2PER; i++) {
            __stcs(&o4[q], z4);
            q += (size_t)K2LANES;
        }
        return;
    }

    // ---- finalize block (scalars live beyond 2*BNEC: outside every zero region) ----
    if (blockIdx.x == 4) {
        if (tid < 256) {
            __shared__ float red[256];
            const int b = tid >> 6, e = tid & 63;

            float dens = 0.f; int cnt = 0;
            #pragma unroll 8
            for (int c = 0; c < 64; c++) {
                dens += g_dens_p[b*64 + c][e];
                cnt  += g_cnt_p[b*64 + c][e];
            }
            red[tid] = dens * (float)cnt;
            for (int s = 128; s > 0; s >>= 1) {
                asm volatile("bar.sync 1, 256;" ::: "memory");
                if (tid < s) red[tid] += red[tid + s];
            }
            asm volatile("bar.sync 1, 256;" ::: "memory");
            float loss = red[0] * ((float)EE / ((float)BB * (float)NN * (float)NN));
            asm volatile("bar.sync 1, 256;" ::: "memory");

            red[tid] = g_lse_p[tid];
            for (int s = 128; s > 0; s >>= 1) {
                asm volatile("bar.sync 1, 256;" ::: "memory");
                if (tid < s) red[tid] += red[tid + s];
            }
            asm volatile("bar.sync 1, 256;" ::: "memory");
            if (tid == 0) {
                out[2*BNEC]     = loss;
                out[2*BNEC + 1] = red[0] * (1.0f / (float)BB);
            }
        }
        return;
    }

    // ---- scan + scatter blocks (one per batch) ----
    __shared__ int s_c1[64][64];     // chunk-hist, overwritten in-place by exclusive prefix
    __shared__ int s_c2[64][64];
    __shared__ int hist1[16][64];    // per-pass lower-half-warp histograms
    __shared__ int hist2[16][64];

    const int b    = blockIdx.x;
    const int wid  = tid >> 5;
    const int lane = tid & 31;
    const unsigned lt = (1u << lane) - 1u;

    // load 64 chunks x 64 experts (int4-coalesced)
    ((int4*)s_c1)[tid] = ((const int4*)g_cnt_p)[b*1024 + tid];
    ((int4*)s_c2)[tid] = ((const int4*)g_cnt2_p)[b*1024 + tid];
    __syncthreads();

    // per-expert exclusive prefix over chunks; phase-2 base = capped phase-1 total
    if (tid < 64) {
        int run = 0;
        #pragma unroll 8
        for (int c = 0; c < 64; c++) { int v = s_c1[c][tid]; s_c1[c][tid] = run; run += v; }
        int run2 = min(run, CAP);
        #pragma unroll 8
        for (int c = 0; c < 64; c++) { int v = s_c2[c][tid]; s_c2[c][tid] = run2; run2 += v; }
    }
    __syncthreads();

    // 4 passes x 1024 tokens; each 64-token chunk spans exactly 2 warps
    for (int pass = 0; pass < 4; pass++) {
        const int li = pass * 1024 + tid;    // token index within batch
        const int t  = b * NN + li;
        const int ch = li >> 6;              // chunk within batch (0..63)
        const int hc = tid >> 6;             // chunk within this pass (0..15)
        const bool upper = (wid & 1);

        ((int*)hist1)[tid] = 0;
        ((int*)hist2)[tid] = 0;
        __syncthreads();

        const int e1    = g_idx1[t];
        const float g2v = g_g2[t];
        const bool v2   = g2v > THRESH;
        const int e2    = v2 ? g_idx2[t] : -1;

        unsigned m1 = __match_any_sync(0xffffffffu, e1);
        int r1 = __popc(m1 & lt);
        unsigned m2 = __match_any_sync(0xffffffffu, e2);
        int r2 = __popc(m2 & lt);

        if (!upper) {
            if (r1 == 0) hist1[hc][e1] = __popc(m1);
            if (v2 && r2 == 0) hist2[hc][e2] = __popc(m2);
        }
        __syncthreads();

        if (upper) {
            r1 += hist1[hc][e1];
            if (v2) r2 += hist2[hc][e2];
        }

        const size_t row = (size_t)t * (EE*CAP);
        const bool safe = (t < T_DEFER);

        const int p1 = s_c1[ch][e1] + r1;
        const int pos1 = (p1 < CAP) ? p1 : -1;
        if (pos1 >= 0) {
            const size_t o = row + (size_t)e1 * CAP + p1;
            out[o] = 1.f;                          // dispatch: always in K1's zero region
            if (safe) out[BNEC + o] = g_g1[t];     // combine: safe only below T_DEFER
        }
        int pos2 = -1;
        if (v2) {
            const int p2 = s_c2[ch][e2] + r2;
            pos2 = (p2 < CAP) ? p2 : -1;
            if (pos2 >= 0) {
                const size_t o = row + (size_t)e2 * CAP + p2;
                out[o] = 1.f;
                if (safe) out[BNEC + o] = g2v;
            }
        }
        if (!safe) { g_pos1[t] = pos1; g_pos2[t] = pos2; }
        __syncthreads();
    }
}

// ---------------- K3: drain deferred combine writes (tokens >= T_DEFER) ----------------
__global__ __launch_bounds__(256) void defer_kernel(float* __restrict__ out) {
    const int t = T_DEFER + blockIdx.x * 256 + threadIdx.x;
    const int p1 = g_pos1[t], p2 = g_pos2[t];
    const size_t row = (size_t)t * (EE*CAP);
    if (p1 >= 0) out[BNEC + row + (size_t)g_idx1[t] * CAP + p1] = g_g1[t];
    if (p2 >= 0) out[BNEC + row + (size_t)g_idx2[t] * CAP + p2] = g_g2[t];
}

// ---------------- launch ----------------
extern "C" void kernel_launch(void* const* d_in, const int* in_sizes, int n_in,
                              void* d_out, int out_size) {
    const float* x = (const float*)d_in[0];   // [4,4096,1024] f32
    const float* w = (const float*)d_in[1];   // [1024,64] f32
    float* out = (float*)d_out;               // dispatch | combine | loss | z_loss

    fused_kernel<<<NB + NZB, 256>>>(x, w, out);
    scan_zero_kernel<<<5 + K2ZB, 1024>>>(out);
    defer_kernel<<<NDEF/256, 256>>>(out);
}

// round 13
// speedup vs baseline: 1.4448x; 1.0394x over previous
#include <cuda_runtime.h>
#include <cstdint>

#define BB 4
#define NN 4096
#define DD 1024
#define EE 64
#define CAP 128
#define NT (BB*NN)                       // 16384 tokens
#define BNEC ((size_t)NT*EE*CAP)         // 134217728 elements per big tensor
#define THRESH 0.2f
#define NB 256                           // gating blocks (64 tokens each)

// zero-fill partition (in float4 units): total = 2*BNEC/4 = 67,108,864
#define TOT4   67108864UL
#define K2Z4   6291456UL                 // 96 MiB handled during scan window
#define K1Z4   (TOT4 - K2Z4)             // 60,817,408 float4
#define NZB    29696                     // K1 zero blocks: 29696 * 2048 = K1Z4
#define K2ZB   384                       // zero blocks in K2
#define K2LANES (K2ZB*1024)              // 393216 lanes * 16 = K2Z4
#define K2PER  16

#define CP_ASYNC16(dst_u32, src_ptr) \
    asm volatile("cp.async.cg.shared.global [%0], [%1], 16;" :: "r"(dst_u32), "l"(src_ptr) : "memory")
#define CP_COMMIT() asm volatile("cp.async.commit_group;" ::: "memory")
#define CP_WAIT(n)  asm volatile("cp.async.wait_group %0;" :: "n"(n) : "memory")

// ---------------- scratch (no allocations allowed) ----------------
__device__ int   g_idx1[NT], g_idx2[NT];
__device__ float g_g1[NT],  g_g2[NT];
__device__ int   g_pos1[NT], g_pos2[NT];
__device__ float g_dens_p[NB][EE];       // per-gating-block partials (no atomics, no init)
__device__ int   g_cnt_p[NB][EE];        // per-chunk top-1 histogram (scan input)
__device__ int   g_cnt2_p[NB][EE];       // per-chunk thresholded top-2 histogram
__device__ float g_lse_p[NB];

// ---------------- K1: heterogeneous blocks ----------------
// bid < NB   : GEMM (4-stage cp.async pipeline) + softmax + top2 + aux + histograms
// bid >= NB  : pure zero-writer block, contiguous 32 KiB (proven 85.7%-DRAM pattern)
__global__ __launch_bounds__(256) void fused_kernel(const float* __restrict__ x,
                                                    const float* __restrict__ w,
                                                    float* __restrict__ out) {
    const int tid = threadIdx.x;
    const int bid = blockIdx.x;

    // ======== zero-writer blocks ========
    if (bid >= NB) {
        const size_t base = (size_t)(bid - NB) * 2048 + tid;
        float4* __restrict__ o4 = (float4*)out;
        const float4 z4 = make_float4(0.f, 0.f, 0.f, 0.f);
        #pragma unroll
        for (int i = 0; i < 8; i++)
            __stcs(&o4[base + (size_t)i * 256], z4);
        return;
    }

    // ======== GEMM blocks: 64 tokens x 64 experts, pipelined loads ========
    // pipeline buffers and gating buffers never live simultaneously -> union
    __shared__ union {
        struct {
            float xs[4][64][16];   // [stage][token][k-within-chunk]  (verbatim gmem layout)
            float ws[4][16][64];   // [stage][k][expert]
        } p;
        struct {
            float logits[64][65];  // padded; overwritten in-place by probs
            float sm_invS[64];
            int   scnt[64];
            int   scnt2[64];
        } g;
    } sm;

    const int t0 = bid * 64;
    const int eg = tid & 15, tg = tid >> 4;

    float acc[4][4];
    #pragma unroll
    for (int i = 0; i < 4; i++)
        #pragma unroll
        for (int j = 0; j < 4; j++) acc[i][j] = 0.f;

    const int xtok = tid >> 2, xkq = tid & 3;   // x loader: 64 tok x 4 quads
    const int wkk  = tid >> 4, weq = tid & 15;  // w loader: 16 k x 16 quads

    // gmem sources (float4 units)
    const float4* xg = (const float4*)(x) + (size_t)(t0 + xtok) * (DD/4) + xkq;
    const float4* wg = (const float4*)(w) + (size_t)wkk * (EE/4) + weq;

    // smem destinations for this thread, per stage
    uint32_t xdst[4], wdst[4];
    #pragma unroll
    for (int s = 0; s < 4; s++) {
        xdst[s] = (uint32_t)__cvta_generic_to_shared(&sm.p.xs[s][xtok][xkq*4]);
        wdst[s] = (uint32_t)__cvta_generic_to_shared(&sm.p.ws[s][wkk][weq*4]);
    }

    // prologue: stages 0..2 in flight
    #pragma unroll
    for (int p = 0; p < 3; p++) {
        CP_ASYNC16(xdst[p], xg + (size_t)p * 4);
        CP_ASYNC16(wdst[p], wg + (size_t)p * 16 * (EE/4));
        CP_COMMIT();
    }

    for (int kc = 0; kc < DD/16; kc++) {
        CP_WAIT(2);             // stage kc's group complete
        __syncthreads();        // visible to all; also: compute on stage kc-1 done everywhere
        if (kc + 3 < DD/16) {
            const int s = (kc + 3) & 3;
            CP_ASYNC16(xdst[s], xg + (size_t)(kc + 3) * 4);
            CP_ASYNC16(wdst[s], wg + (size_t)(kc + 3) * 16 * (EE/4));
        }
        CP_COMMIT();            // unguarded: keeps group counting uniform

        const int s = kc & 3;
        #pragma unroll
        for (int kq = 0; kq < 4; kq++) {
            float4 av[4];
            #pragma unroll
            for (int i = 0; i < 4; i++)
                av[i] = *(const float4*)&sm.p.xs[s][tg*4 + i][kq*4];
            #pragma unroll
            for (int kk = 0; kk < 4; kk++) {
                const float4 bv = *(const float4*)&sm.p.ws[s][kq*4 + kk][eg*4];
                #pragma unroll
                for (int i = 0; i < 4; i++) {
                    const float ai = ((const float*)&av[i])[kk];
                    acc[i][0] += ai * bv.x;
                    acc[i][1] += ai * bv.y;
                    acc[i][2] += ai * bv.z;
                    acc[i][3] += ai * bv.w;
                }
            }
        }
    }

    CP_WAIT(0);
    __syncthreads();            // pipeline dead; union may flip to gating

    #pragma unroll
    for (int i = 0; i < 4; i++)
        #pragma unroll
        for (int j = 0; j < 4; j++)
            sm.g.logits[tg*4 + i][eg*4 + j] = acc[i][j];

    if (tid < 64) { sm.g.scnt[tid] = 0; sm.g.scnt2[tid] = 0; }
    __syncthreads();

    float my_lse = 0.f;
    if (tid < 64) {
        const int t = tid;
        // top-2 over logits (softmax monotonic; strict > keeps first index on ties)
        float best1 = -3.4e38f, best2 = -3.4e38f;
        int i1 = 0, i2 = 0;
        #pragma unroll 4
        for (int e = 0; e < EE; e++) {
            float l = sm.g.logits[t][e];
            if (l > best1) { best2 = best1; i2 = i1; best1 = l; i1 = e; }
            else if (l > best2) { best2 = l; i2 = e; }
        }
        float S = 0.f;
        #pragma unroll 4
        for (int e = 0; e < EE; e++) {
            float p = __expf(sm.g.logits[t][e] - best1);
            sm.g.logits[t][e] = p;               // in-place: row t owned by thread t
            S += p;
        }
        float invS = 1.0f / S;
        sm.g.sm_invS[t] = invS;
        float g1 = invS;                         // exp(best1-best1)*invS
        float g2 = __expf(best2 - best1) * invS;
        float denom = g1 + g2 + 1e-9f;
        float g1n = g1 / denom, g2n = g2 / denom;
        g_idx1[t0 + t] = i1;
        g_idx2[t0 + t] = i2;
        g_g1[t0 + t] = g1n;
        g_g2[t0 + t] = g2n;
        atomicAdd(&sm.g.scnt[i1], 1);
        if (g2n > THRESH) atomicAdd(&sm.g.scnt2[i2], 1);
        my_lse = best1 + __logf(S);
    }
    __syncthreads();

    if (tid < 64) {
        // density: column sums of the in-place prob matrix
        float s = 0.f;
        #pragma unroll 4
        for (int t = 0; t < 64; t++) s += sm.g.logits[t][tid] * sm.g.sm_invS[t];
        g_dens_p[bid][tid] = s;
        g_cnt_p[bid][tid]  = sm.g.scnt[tid];
        g_cnt2_p[bid][tid] = sm.g.scnt2[tid];
        // warp-reduce lse across the 2 warps holding tid<64
        #pragma unroll
        for (int o = 16; o > 0; o >>= 1)
            my_lse += __shfl_down_sync(0xffffffffu, my_lse, o);
        if ((tid & 31) == 0) {
            if (tid == 0) sm.g.sm_invS[0] = my_lse;   // reuse smem slot
            else          sm.g.sm_invS[1] = my_lse;
        }
    }
    __syncthreads();
    if (tid == 0) g_lse_p[bid] = sm.g.sm_invS[0] + sm.g.sm_invS[1];
}

// ---------------- K2: chunk-parallel scan (blocks 0..3) + zero-fill (blocks 4..387) ----------------
__global__ __launch_bounds__(1024) void scan_zero_kernel(float* __restrict__ out) {
    // ---- zero-fill blocks: cover the last 96 MiB while the scan runs ----
    if (blockIdx.x >= 4) {
        const unsigned lane = (blockIdx.x - 4) * 1024u + threadIdx.x;
        float4* __restrict__ o4 = (float4*)out + K1Z4;
        const float4 z4 = make_float4(0.f, 0.f, 0.f, 0.f);
        size_t q = lane;
        #pragma unroll
        for (int i = 0; i < K2PER; i++) {
            __stcs(&o4[q], z4);
            q += (size_t)K2LANES;
        }
        return;
    }

    __shared__ int s_c1[64][64];     // chunk-hist, overwritten in-place by exclusive prefix
    __shared__ int s_c2[64][64];
    __shared__ int hist1[16][64];    // per-pass lower-half-warp histograms
    __shared__ int hist2[16][64];

    const int b    = blockIdx.x;
    const int tid  = threadIdx.x;
    const int wid  = tid >> 5;
    const int lane = tid & 31;
    const unsigned lt = (1u << lane) - 1u;

    // load 64 chunks x 64 experts (int4-coalesced)
    ((int4*)s_c1)[tid] = ((const int4*)g_cnt_p)[b*1024 + tid];
    ((int4*)s_c2)[tid] = ((const int4*)g_cnt2_p)[b*1024 + tid];
    __syncthreads();

    // per-expert exclusive prefix over chunks; phase-2 base = capped phase-1 total
    if (tid < 64) {
        int run = 0;
        #pragma unroll 8
        for (int c = 0; c < 64; c++) { int v = s_c1[c][tid]; s_c1[c][tid] = run; run += v; }
        int run2 = min(run, CAP);
        #pragma unroll 8
        for (int c = 0; c < 64; c++) { int v = s_c2[c][tid]; s_c2[c][tid] = run2; run2 += v; }
    }
    __syncthreads();

    // 4 passes x 1024 tokens; each 64-token chunk spans exactly 2 warps
    for (int pass = 0; pass < 4; pass++) {
        const int li = pass * 1024 + tid;    // token index within batch
        const int t  = b * NN + li;
        const int ch = li >> 6;              // chunk within batch (0..63)
        const int hc = tid >> 6;             // chunk within this pass (0..15)
        const bool upper = (wid & 1);

        ((int*)hist1)[tid] = 0;
        ((int*)hist2)[tid] = 0;
        __syncthreads();

        const int e1   = g_idx1[t];
        const bool v2  = g_g2[t] > THRESH;
        const int e2   = v2 ? g_idx2[t] : -1;

        unsigned m1 = __match_any_sync(0xffffffffu, e1);
        int r1 = __popc(m1 & lt);
        unsigned m2 = __match_any_sync(0xffffffffu, e2);
        int r2 = __popc(m2 & lt);

        if (!upper) {
            if (r1 == 0) hist1[hc][e1] = __popc(m1);
            if (v2 && r2 == 0) hist2[hc][e2] = __popc(m2);
        }
        __syncthreads();

        if (upper) {
            r1 += hist1[hc][e1];
            if (v2) r2 += hist2[hc][e2];
        }

        int p1 = s_c1[ch][e1] + r1;
        g_pos1[t] = (p1 < CAP) ? p1 : -1;
        if (v2) {
            int p2 = s_c2[ch][e2] + r2;
            g_pos2[t] = (p2 < CAP) ? p2 : -1;
        } else {
            g_pos2[t] = -1;
        }
        __syncthreads();
    }
}

// ---------------- K3: scatter nonzeros + finalize scalars (block 0) ----------------
__global__ __launch_bounds__(256) void scatter_finalize_kernel(float* __restrict__ out) {
    const int t = blockIdx.x * 256 + threadIdx.x;

    if (t < NT) {
        const int p1 = g_pos1[t], p2 = g_pos2[t];
        const size_t row = (size_t)t * (EE*CAP);

        if (p1 >= 0) {
            const size_t o = row + (size_t)g_idx1[t] * CAP + p1;
            out[o]        = 1.f;       // dispatch
            out[BNEC + o] = g_g1[t];   // combine
        }
        if (p2 >= 0) {
            const size_t o = row + (size_t)g_idx2[t] * CAP + p2;
            out[o]        = 1.f;
            out[BNEC + o] = g_g2[t];
        }
    }

    if (blockIdx.x == 0) {
        __shared__ float red[256];
        const int tid = threadIdx.x;
        const int b = tid >> 6, e = tid & 63;

        // reconstruct per-(batch,expert) dens & count from the 64 chunk partials
        float dens = 0.f; int cnt = 0;
        #pragma unroll 8
        for (int c = 0; c < 64; c++) {
            dens += g_dens_p[b*64 + c][e];
            cnt  += g_cnt_p[b*64 + c][e];
        }
        red[tid] = dens * (float)cnt;
        __syncthreads();
        for (int s = 128; s > 0; s >>= 1) {
            if (tid < s) red[tid] += red[tid + s];
            __syncthreads();
        }
        float loss = red[0] * ((float)EE / ((float)BB * (float)NN * (float)NN));
        __syncthreads();

        red[tid] = g_lse_p[tid];
        __syncthreads();
        for (int s = 128; s > 0; s >>= 1) {
            if (tid < s) red[tid] += red[tid + s];
            __syncthreads();
        }
        if (tid == 0) {
            out[2*BNEC]     = loss;
            out[2*BNEC + 1] = red[0] * (1.0f / (float)BB);
        }
    }
}

// ---------------- launch ----------------
extern "C" void kernel_launch(void* const* d_in, const int* in_sizes, int n_in,
                              void* d_out, int out_size) {
    const float* x = (const float*)d_in[0];   // [4,4096,1024] f32
    const float* w = (const float*)d_in[1];   // [1024,64] f32
    float* out = (float*)d_out;               // dispatch | combine | loss | z_loss

    fused_kernel<<<NB + NZB, 256>>>(x, w, out);
    scan_zero_kernel<<<4 + K2ZB, 1024>>>(out);
    scatter_finalize_kernel<<<NT/256, 256>>>(out);
}